// round 3
// baseline (speedup 1.0000x reference)
#include <cuda_runtime.h>
#include <cuda_bf16.h>

#define T_STEPS 32768
#define IN_SIZE 1024
#define HID     64
#define GATES   256   // 4 * HID

// Scratch: precomputed input projection, (T, 4H) row-major. 33.5 MB static.
__device__ float g_xproj[T_STEPS * GATES];

// ---------------------------------------------------------------------------
// Kernel 1: x_proj[t][j] = sum_k spec[k][t] * W_ih[j][k] + b_ih[j] + b_hh[j]
// Tiled FP32 GEMM: block = 64 timesteps x 256 gates, BK = 8, 256 threads,
// each thread computes an 8x8 (t x j) micro-tile.
// ---------------------------------------------------------------------------
__global__ void __launch_bounds__(256, 1)
gemm_xproj_kernel(const float* __restrict__ spec,
                  const float* __restrict__ W_ih,
                  const float* __restrict__ b_ih,
                  const float* __restrict__ b_hh)
{
    __shared__ float sS[8][64];    // [kk][t]
    __shared__ float sW[8][GATES]; // [kk][j]

    const int tid = threadIdx.x;
    const int t0  = blockIdx.x * 64;
    const int tj  = (tid & 31) * 8;  // j base (0..248)
    const int tt  = (tid >> 5) * 8;  // t base within tile (0..56)

    float acc[8][8];
#pragma unroll
    for (int i = 0; i < 8; i++)
#pragma unroll
        for (int j = 0; j < 8; j++) acc[i][j] = 0.f;

    const int krow = tid >> 6;   // 0..3
    const int tcol = tid & 63;   // 0..63

    for (int k0 = 0; k0 < IN_SIZE; k0 += 8) {
        sS[krow][tcol]     = spec[(k0 + krow) * T_STEPS + t0 + tcol];
        sS[krow + 4][tcol] = spec[(k0 + krow + 4) * T_STEPS + t0 + tcol];
        float4 wa = *reinterpret_cast<const float4*>(W_ih + (size_t)tid * IN_SIZE + k0);
        float4 wb = *reinterpret_cast<const float4*>(W_ih + (size_t)tid * IN_SIZE + k0 + 4);
        sW[0][tid] = wa.x; sW[1][tid] = wa.y; sW[2][tid] = wa.z; sW[3][tid] = wa.w;
        sW[4][tid] = wb.x; sW[5][tid] = wb.y; sW[6][tid] = wb.z; sW[7][tid] = wb.w;
        __syncthreads();

#pragma unroll
        for (int kk = 0; kk < 8; kk++) {
            float4 s0 = *reinterpret_cast<const float4*>(&sS[kk][tt]);
            float4 s1 = *reinterpret_cast<const float4*>(&sS[kk][tt + 4]);
            float4 w0 = *reinterpret_cast<const float4*>(&sW[kk][tj]);
            float4 w1 = *reinterpret_cast<const float4*>(&sW[kk][tj + 4]);
            float sv[8] = {s0.x, s0.y, s0.z, s0.w, s1.x, s1.y, s1.z, s1.w};
            float wv[8] = {w0.x, w0.y, w0.z, w0.w, w1.x, w1.y, w1.z, w1.w};
#pragma unroll
            for (int i = 0; i < 8; i++)
#pragma unroll
                for (int j = 0; j < 8; j++)
                    acc[i][j] = fmaf(sv[i], wv[j], acc[i][j]);
        }
        __syncthreads();
    }

    float bias[8];
#pragma unroll
    for (int j = 0; j < 8; j++) bias[j] = b_ih[tj + j] + b_hh[tj + j];

#pragma unroll
    for (int i = 0; i < 8; i++) {
        const int t = t0 + tt + i;
        float4 o0, o1;
        o0.x = acc[i][0] + bias[0]; o0.y = acc[i][1] + bias[1];
        o0.z = acc[i][2] + bias[2]; o0.w = acc[i][3] + bias[3];
        o1.x = acc[i][4] + bias[4]; o1.y = acc[i][5] + bias[5];
        o1.z = acc[i][6] + bias[6]; o1.w = acc[i][7] + bias[7];
        *reinterpret_cast<float4*>(&g_xproj[(size_t)t * GATES + tj])     = o0;
        *reinterpret_cast<float4*>(&g_xproj[(size_t)t * GATES + tj + 4]) = o1;
    }
}

// ---------------------------------------------------------------------------
// HW tanh (MUFU.TANH, single op) + derived sigmoid.
//   sigmoid(x) = 0.5 * tanh(0.5 x) + 0.5
// ---------------------------------------------------------------------------
__device__ __forceinline__ float htanh(float x) {
    float r;
    asm("tanh.approx.f32 %0, %1;" : "=f"(r) : "f"(x));
    return r;
}

// Packed f32x2 FMA: acc = a * b + acc
__device__ __forceinline__ void ffma2(unsigned long long& acc,
                                      unsigned long long a,
                                      unsigned long long b) {
    asm("fma.rn.f32x2 %0, %1, %2, %0;" : "+l"(acc) : "l"(a), "l"(b));
}
__device__ __forceinline__ float red2(unsigned long long a,
                                      unsigned long long b) {
    unsigned long long s;
    asm("add.rn.f32x2 %0, %1, %2;" : "=l"(s) : "l"(a), "l"(b));
    float lo, hi;
    asm("mov.b64 {%0, %1}, %2;" : "=f"(lo), "=f"(hi) : "l"(s));
    return lo + hi;
}

// ---------------------------------------------------------------------------
// Kernel 2: sequential LSTM, single block of 128 threads (4 warps).
// Thread = (unit u = tid>>1, pair p = tid&1).
//   p=0 owns gate rows {i: u, f: 64+u};  p=1 owns {g: 128+u, o: 192+u}.
// One set of h loads feeds both rows (8 broadcast LDS.128 per thread).
// Gate exchange between the pair: 2x shfl.xor(1). All activations via
// MUFU.TANH. Double-buffered h -> one __syncthreads per step.
// ---------------------------------------------------------------------------
__global__ void __launch_bounds__(128, 1)
lstm_seq_kernel(const float* __restrict__ W_hh, float* __restrict__ out)
{
    __shared__ __align__(16) float h_sh[2][HID];

    const int tid = threadIdx.x;
    const int u   = tid >> 1;      // unit 0..63
    const int p   = tid & 1;       // 0: {i,f}, 1: {g,o}
    const int r0  = p * 2 * HID + u;        // row of gate i (p=0) / g (p=1)
    const int r1  = p * 2 * HID + HID + u;  // row of gate f (p=0) / o (p=1)

    // Load both weight rows into registers as packed f32 pairs (64 ull)
    unsigned long long w0q[HID / 2], w1q[HID / 2];
    {
        const ulonglong2* wp0 =
            reinterpret_cast<const ulonglong2*>(W_hh + (size_t)r0 * HID);
        const ulonglong2* wp1 =
            reinterpret_cast<const ulonglong2*>(W_hh + (size_t)r1 * HID);
#pragma unroll
        for (int i = 0; i < HID / 4; i++) {    // 16 x ulonglong2 per row
            ulonglong2 v0 = wp0[i];
            ulonglong2 v1 = wp1[i];
            w0q[2 * i] = v0.x; w0q[2 * i + 1] = v0.y;
            w1q[2 * i] = v1.x; w1q[2 * i + 1] = v1.y;
        }
    }

    // Activation folding for act0:  p=0 -> sigmoid, p=1 -> tanh
    //   act = q * tanh(m * a) + r   with (m,q,r) = (0.5,0.5,0.5) or (1,1,0)
    const float m0 = p ? 1.f : 0.5f;
    const float q0 = p ? 1.f : 0.5f;
    const float r0c = p ? 0.f : 0.5f;

    float c = 0.f;
    if (tid < HID) h_sh[0][tid] = 0.f;

    float xn0 = g_xproj[r0];           // t = 0 prefetch
    float xn1 = g_xproj[r1];
    __syncthreads();

    for (int t = 0; t < T_STEPS; t++) {
        const int rbuf = t & 1;
        const float xp0 = xn0, xp1 = xn1;
        const int tn = (t + 1 < T_STEPS) ? (t + 1) : t;
        xn0 = g_xproj[(size_t)tn * GATES + r0];   // prefetch next step
        xn1 = g_xproj[(size_t)tn * GATES + r1];

        // Two matvec rows sharing one h load stream (broadcast LDS.128)
        unsigned long long a00 = 0ull, a01 = 0ull, a10 = 0ull, a11 = 0ull;
        const ulonglong2* hp =
            reinterpret_cast<const ulonglong2*>(&h_sh[rbuf][0]);
#pragma unroll
        for (int k = 0; k < HID / 8; k++) {   // 8 iters, 8 LDS.128 total
            ulonglong2 hA = hp[2 * k];
            ulonglong2 hB = hp[2 * k + 1];
            ffma2(a00, hA.x, w0q[4 * k]);
            ffma2(a01, hA.y, w0q[4 * k + 1]);
            ffma2(a10, hA.x, w1q[4 * k]);
            ffma2(a11, hA.y, w1q[4 * k + 1]);
            ffma2(a00, hB.x, w0q[4 * k + 2]);
            ffma2(a01, hB.y, w0q[4 * k + 3]);
            ffma2(a10, hB.x, w1q[4 * k + 2]);
            ffma2(a11, hB.y, w1q[4 * k + 3]);
        }
        const float a0 = xp0 + red2(a00, a01);
        const float a1 = xp1 + red2(a10, a11);

        // Own activations: v0 = sigm/tanh(a0), v1 = sigm(a1). 2 MUFU ops.
        const float v0 = fmaf(q0, htanh(m0 * a0), r0c);
        const float v1 = fmaf(0.5f, htanh(0.5f * a1), 0.5f);

        // Exchange with pair partner (lane^1)
        const float b0 = __shfl_xor_sync(0xffffffffu, v0, 1);
        const float b1 = __shfl_xor_sync(0xffffffffu, v1, 1);
        const float gi = p ? b0 : v0;
        const float gf = p ? b1 : v1;
        const float gg = p ? v0 : b0;
        const float go = p ? v1 : b1;

        // Both pair threads track c redundantly (identical values)
        c = fmaf(gf, c, gi * gg);
        const float th = htanh(c);           // 1 MUFU op
        if (p == 0) h_sh[rbuf ^ 1][u] = go * th;

        __syncthreads();
    }

    // log_softmax over final h (accurate libm; runs once). Final h in buf 0.
    if (tid < HID) {
        const float* hf = h_sh[T_STEPS & 1];
        float m = -1e30f;
#pragma unroll 8
        for (int k = 0; k < HID; k++) m = fmaxf(m, hf[k]);
        float sum = 0.f;
#pragma unroll 8
        for (int k = 0; k < HID; k++) sum += expf(hf[k] - m);
        out[tid] = hf[tid] - m - logf(sum);
    }
}

// ---------------------------------------------------------------------------
// Launch: inputs in metadata order: spectrogram, W_ih, W_hh, b_ih, b_hh
// ---------------------------------------------------------------------------
extern "C" void kernel_launch(void* const* d_in, const int* in_sizes, int n_in,
                              void* d_out, int out_size)
{
    const float* spec = (const float*)d_in[0];
    const float* W_ih = (const float*)d_in[1];
    const float* W_hh = (const float*)d_in[2];
    const float* b_ih = (const float*)d_in[3];
    const float* b_hh = (const float*)d_in[4];
    float* out = (float*)d_out;

    gemm_xproj_kernel<<<T_STEPS / 64, 256>>>(spec, W_ih, b_ih, b_hh);
    lstm_seq_kernel<<<1, 128>>>(W_hh, out);
}